// round 4
// baseline (speedup 1.0000x reference)
#include <cuda_runtime.h>

// Problem constants (B=8, C=19, H=512, W=512)
#define CLS    19
#define NBINS  65536
#define HW     262144          // 512*512 = 2^18
#define PIX    2097152         // 8*HW

// Scratch (device globals; no allocation allowed)
__device__ unsigned int g_cntA[CLS * NBINS];   // fg==1 (label class) error counts
__device__ unsigned int g_cntB[CLS * NBINS];   // fg==0 error counts
__device__ double       g_loss[CLS];
__device__ unsigned int g_pres[CLS];
__device__ int          g_lab64;               // 1 if labels are int64, 0 if int32

__global__ void zero_kernel() {
    int i = blockIdx.x * blockDim.x + threadIdx.x;
    if (i < CLS * NBINS) {
        g_cntA[i] = 0u;
        g_cntB[i] = 0u;
    }
}

// Detect label dtype: if labels are little-endian int64 with values 0..18, every
// odd 32-bit word is zero. If int32, odd words are labels (nonzero w.p. 18/19 each).
__global__ void detect_kernel(const unsigned int* __restrict__ lab32) {
    __shared__ unsigned int s;
    if (threadIdx.x == 0) s = 0u;
    __syncthreads();
    unsigned int w = lab32[threadIdx.x * 2 + 1];
    // warp-reduce then one atomic per warp
    for (int off = 16; off; off >>= 1)
        w |= __shfl_down_sync(0xffffffffu, w, off);
    if ((threadIdx.x & 31) == 0) atomicOr(&s, w);
    __syncthreads();
    if (threadIdx.x == 0) g_lab64 = (s == 0u) ? 1 : 0;
}

// Fused softmax + binning. One thread per pixel; 19 channel values in registers.
__global__ void __launch_bounds__(256) hist_kernel(const float* __restrict__ x,
                                                   const void* __restrict__ lab) {
    int p = blockIdx.x * blockDim.x + threadIdx.x;
    if (p >= PIX) return;
    int b  = p >> 18;            // p / HW
    int hw = p & (HW - 1);
    size_t base = ((size_t)b * CLS) * (size_t)HW + (size_t)hw;

    float v[CLS];
    float m = -1e30f;
#pragma unroll
    for (int c = 0; c < CLS; c++) {
        v[c] = x[base + (size_t)c * HW];
        m = fmaxf(m, v[c]);
    }
    float s = 0.f;
#pragma unroll
    for (int c = 0; c < CLS; c++) {
        v[c] = __expf(v[c] - m);
        s += v[c];
    }
    float invZ = 1.0f / s;

    int l = g_lab64 ? (int)((const long long*)lab)[p]
                    : ((const int*)lab)[p];

#pragma unroll
    for (int c = 0; c < CLS; c++) {
        float pc = v[c] * invZ;
        bool isA = (c == l);
        float e = isA ? (1.0f - pc) : pc;
        e = fminf(fmaxf(e, 0.0f), 1.0f);
        int q = (int)(e * (float)NBINS);
        q = q > (NBINS - 1) ? (NBINS - 1) : q;
        unsigned int* h = isA ? g_cntA : g_cntB;
        atomicAdd(&h[c * NBINS + q], 1u);     // RED.E.ADD.32 (result unused)
    }
}

// Per-class descending scan over bins; closed-form Lovasz loss.
//
// For descending-sorted errors with fg flags: an A-element (fg=1) with N B's
// strictly above contributes e/(G+N); a B-element with F A's and N B's above
// contributes e*(G-F)/((G+N)(G+N+1)). Within a bin the B-steps telescope:
// sum_{j=0}^{nB-1} 1/((GN+j)(GN+j+1)) = 1/GN - 1/(GN+nB). Unknown within-bin
// interleaving is handled by midpoint correction (error << 1e-3).
__global__ void __launch_bounds__(1024) scan_kernel() {
    const int RPT = NBINS / 1024;   // 64 bins per thread
    int c = blockIdx.x;
    int t = threadIdx.x;
    int base = c * NBINS;
    int r0 = t * RPT;

    __shared__ unsigned int shA[1024];
    __shared__ unsigned int shB[1024];

    // Pass 1: local counts (descending rank r -> bin NBINS-1-r)
    unsigned int la = 0, lb = 0;
    for (int i = 0; i < RPT; i++) {
        int q = NBINS - 1 - (r0 + i);
        la += g_cntA[base + q];
        lb += g_cntB[base + q];
    }
    shA[t] = la; shB[t] = lb;
    __syncthreads();

    // Inclusive block scan (Hillis-Steele)
    for (int off = 1; off < 1024; off <<= 1) {
        unsigned int va = 0, vb = 0;
        if (t >= off) { va = shA[t - off]; vb = shB[t - off]; }
        __syncthreads();
        shA[t] += va; shB[t] += vb;
        __syncthreads();
    }
    unsigned int totA = shA[1023];
    unsigned int excA = shA[t] - la;   // A's strictly above this thread's segment
    unsigned int excB = shB[t] - lb;

    double G = (double)totA;
    double loss = 0.0;
    unsigned int F = excA, N = excB;
    const double binw = 1.0 / (double)NBINS;

    for (int i = 0; i < RPT; i++) {
        int q = NBINS - 1 - (r0 + i);
        unsigned int nA = g_cntA[base + q];
        unsigned int nB = g_cntB[base + q];
        if (nA | nB) {
            double eq = ((double)q + 0.5) * binw;   // bin-center error value
            double GN = G + (double)N;
            if (nA) {
                // A-step gradient 1/(G+N); midpoint over interleaved B's in bin
                loss += (double)nA * eq / (GN + 0.5 * (double)nB);
            }
            if (nB) {
                loss += eq *
                        (G - (double)F - 0.5 * (double)nA) *
                        (1.0 / GN - 1.0 / (GN + (double)nB));
            }
            F += nA; N += nB;
        }
    }

    // Block-reduce the double accumulator
    for (int off = 16; off; off >>= 1)
        loss += __shfl_down_sync(0xffffffffu, loss, off);
    __shared__ double warpS[32];
    if ((t & 31) == 0) warpS[t >> 5] = loss;
    __syncthreads();
    if (t < 32) {
        double v2 = warpS[t];
        for (int off = 16; off; off >>= 1)
            v2 += __shfl_down_sync(0xffffffffu, v2, off);
        if (t == 0) {
            g_loss[c] = v2;
            g_pres[c] = (totA > 0u) ? 1u : 0u;
        }
    }
}

__global__ void final_kernel(float* out) {
    int t = threadIdx.x;
    double l = 0.0, pcnt = 0.0;
    if (t < CLS && g_pres[t]) { l = g_loss[t]; pcnt = 1.0; }
    for (int off = 16; off; off >>= 1) {
        l    += __shfl_down_sync(0xffffffffu, l, off);
        pcnt += __shfl_down_sync(0xffffffffu, pcnt, off);
    }
    if (t == 0) out[0] = (float)(l / (pcnt > 0.0 ? pcnt : 1.0));
}

extern "C" void kernel_launch(void* const* d_in, const int* in_sizes, int n_in,
                              void* d_out, int out_size) {
    const float* x   = (const float*)d_in[0];
    const void*  lab = d_in[1];
    float*       out = (float*)d_out;

    (void)in_sizes; (void)n_in; (void)out_size;

    zero_kernel<<<(CLS * NBINS + 255) / 256, 256>>>();
    detect_kernel<<<1, 256>>>((const unsigned int*)lab);
    hist_kernel<<<PIX / 256, 256>>>(x, lab);
    scan_kernel<<<CLS, 1024>>>();
    final_kernel<<<1, 32>>>(out);
}

// round 6
// speedup vs baseline: 1.2278x; 1.2278x over previous
#include <cuda_runtime.h>

// Problem constants (B=8, C=19, H=512, W=512)
#define CLS    19
#define NBINS  65536
#define HW     262144          // 512*512 = 2^18
#define PIX    2097152         // 8*HW

// Scratch (device globals; no allocation allowed)
__device__ unsigned int g_cntA[CLS * NBINS];   // fg==1 (label class) error counts
__device__ unsigned int g_cntB[CLS * NBINS];   // fg==0 error counts
__device__ double       g_loss[CLS];
__device__ unsigned int g_pres[CLS];
__device__ int          g_lab64;               // 1 if labels are int64, 0 if int32

__global__ void zero_kernel() {
    int i = blockIdx.x * blockDim.x + threadIdx.x;
    if (i < CLS * NBINS) {
        g_cntA[i] = 0u;
        g_cntB[i] = 0u;
    }
}

// Detect label dtype: if labels are little-endian int64 with values 0..18, every
// odd 32-bit word is zero. If int32, odd words are labels (nonzero w.p. 18/19 each).
__global__ void detect_kernel(const unsigned int* __restrict__ lab32) {
    __shared__ unsigned int s;
    if (threadIdx.x == 0) s = 0u;
    __syncthreads();
    unsigned int w = lab32[threadIdx.x * 2 + 1];
    for (int off = 16; off; off >>= 1)
        w |= __shfl_down_sync(0xffffffffu, w, off);
    if ((threadIdx.x & 31) == 0) atomicOr(&s, w);
    __syncthreads();
    if (threadIdx.x == 0) g_lab64 = (s == 0u) ? 1 : 0;
}

// Fused softmax + binning. One thread per pixel; 19 channel values in registers.
__global__ void __launch_bounds__(256) hist_kernel(const float* __restrict__ x,
                                                   const void* __restrict__ lab) {
    int p = blockIdx.x * blockDim.x + threadIdx.x;
    if (p >= PIX) return;
    int b  = p >> 18;            // p / HW
    int hw = p & (HW - 1);
    size_t base = ((size_t)b * CLS) * (size_t)HW + (size_t)hw;

    float v[CLS];
    float m = -1e30f;
#pragma unroll
    for (int c = 0; c < CLS; c++) {
        v[c] = x[base + (size_t)c * HW];
        m = fmaxf(m, v[c]);
    }
    float s = 0.f;
#pragma unroll
    for (int c = 0; c < CLS; c++) {
        v[c] = __expf(v[c] - m);
        s += v[c];
    }
    float invZ = 1.0f / s;

    int l = g_lab64 ? (int)((const long long*)lab)[p]
                    : ((const int*)lab)[p];

#pragma unroll
    for (int c = 0; c < CLS; c++) {
        float pc = v[c] * invZ;
        bool isA = (c == l);
        float e = isA ? (1.0f - pc) : pc;
        e = fminf(fmaxf(e, 0.0f), 1.0f);
        int q = (int)(e * (float)NBINS);
        q = q > (NBINS - 1) ? (NBINS - 1) : q;
        unsigned int* h = isA ? g_cntA : g_cntB;
        atomicAdd(&h[c * NBINS + q], 1u);     // RED.E.ADD.32 (no return)
    }
}

// Per-class descending scan over bins; closed-form Lovasz loss.
//
// Descending-sorted errors with fg flags: an A-element (fg=1) with N B's
// strictly above contributes e/(G+N); a B-element with F A's and N B's above
// contributes e*(G-F)/((G+N)(G+N+1)). Within a bin the B-steps telescope:
// sum_{j=0}^{nB-1} 1/((GN+j)(GN+j+1)) = nB/(GN*(GN+nB))  [no cancellation].
// Unknown within-bin interleave handled by midpoint correction (err << 1e-3).
// All per-bin math in fp32 (GN<=2^21 exact in float); fp64 only as accumulator.
__global__ void __launch_bounds__(1024) scan_kernel() {
    const int RPT = NBINS / 1024;   // 64 bins per thread
    int c = blockIdx.x;
    int t = threadIdx.x;
    int base = c * NBINS;
    int r0 = t * RPT;

    __shared__ unsigned int shA[1024];
    __shared__ unsigned int shB[1024];

    // Pass 1: local counts (descending rank r -> bin NBINS-1-r)
    unsigned int la = 0, lb = 0;
    for (int i = 0; i < RPT; i++) {
        int q = NBINS - 1 - (r0 + i);
        la += g_cntA[base + q];
        lb += g_cntB[base + q];
    }
    shA[t] = la; shB[t] = lb;
    __syncthreads();

    // Inclusive block scan (Hillis-Steele)
    for (int off = 1; off < 1024; off <<= 1) {
        unsigned int va = 0, vb = 0;
        if (t >= off) { va = shA[t - off]; vb = shB[t - off]; }
        __syncthreads();
        shA[t] += va; shB[t] += vb;
        __syncthreads();
    }
    unsigned int totA = shA[1023];
    unsigned int excA = shA[t] - la;   // A's strictly above this thread's segment
    unsigned int excB = shB[t] - lb;

    const float Gf = (float)totA;
    const float binw = 1.0f / (float)NBINS;
    double loss = 0.0;
    unsigned int F = excA, N = excB;

    for (int i = 0; i < RPT; i++) {
        int q = NBINS - 1 - (r0 + i);
        unsigned int nA = g_cntA[base + q];
        unsigned int nB = g_cntB[base + q];
        if (nA | nB) {
            float eq  = ((float)q + 0.5f) * binw;       // bin-center error
            float fnA = (float)nA, fnB = (float)nB;
            float GN  = Gf + (float)N;                  // exact (<2^24)
            float term = 0.0f;
            if (nA) {
                // A-steps: grad 1/(G+N); midpoint over interleaved B's in bin
                term += fnA * eq * __fdividef(1.0f, GN + 0.5f * fnB);
            }
            if (nB) {
                // telescoped B-steps: (G-F)*(1/GN - 1/(GN+nB)), analytic form
                term += eq * (Gf - (float)F - 0.5f * fnA) * fnB *
                        __fdividef(1.0f, GN * (GN + fnB));
            }
            loss += (double)term;
            F += nA; N += nB;
        }
    }

    // Block-reduce the double accumulator
    for (int off = 16; off; off >>= 1)
        loss += __shfl_down_sync(0xffffffffu, loss, off);
    __shared__ double warpS[32];
    if ((t & 31) == 0) warpS[t >> 5] = loss;
    __syncthreads();
    if (t < 32) {
        double v2 = warpS[t];
        for (int off = 16; off; off >>= 1)
            v2 += __shfl_down_sync(0xffffffffu, v2, off);
        if (t == 0) {
            g_loss[c] = v2;
            g_pres[c] = (totA > 0u) ? 1u : 0u;
        }
    }
}

__global__ void final_kernel(float* out) {
    int t = threadIdx.x;
    double l = 0.0, pcnt = 0.0;
    if (t < CLS && g_pres[t]) { l = g_loss[t]; pcnt = 1.0; }
    for (int off = 16; off; off >>= 1) {
        l    += __shfl_down_sync(0xffffffffu, l, off);
        pcnt += __shfl_down_sync(0xffffffffu, pcnt, off);
    }
    if (t == 0) out[0] = (float)(l / (pcnt > 0.0 ? pcnt : 1.0));
}

extern "C" void kernel_launch(void* const* d_in, const int* in_sizes, int n_in,
                              void* d_out, int out_size) {
    const float* x   = (const float*)d_in[0];
    const void*  lab = d_in[1];
    float*       out = (float*)d_out;

    (void)in_sizes; (void)n_in; (void)out_size;

    zero_kernel<<<(CLS * NBINS + 255) / 256, 256>>>();
    detect_kernel<<<1, 256>>>((const unsigned int*)lab);
    hist_kernel<<<PIX / 256, 256>>>(x, lab);
    scan_kernel<<<CLS, 1024>>>();
    final_kernel<<<1, 32>>>(out);
}

// round 7
// speedup vs baseline: 1.6910x; 1.3772x over previous
#include <cuda_runtime.h>

// Problem constants (B=8, C=19, H=512, W=512)
#define CLS    19
#define NBINS  8192
#define HW     262144          // 512*512 = 2^18
#define PIX    2097152         // 8*HW

// Scratch (device globals; no allocation allowed)
__device__ unsigned int g_cntA[CLS * NBINS];   // fg==1 (label class) error counts
__device__ unsigned int g_cntB[CLS * NBINS];   // fg==0 error counts
__device__ double       g_loss[CLS];
__device__ unsigned int g_pres[CLS];
__device__ int          g_lab64;               // 1 if labels are int64, 0 if int32

__global__ void zero_kernel() {
    int i = blockIdx.x * blockDim.x + threadIdx.x;
    if (i < CLS * NBINS) {
        g_cntA[i] = 0u;
        g_cntB[i] = 0u;
    }
}

// Detect label dtype: int64 labels 0..18 have all-zero odd 32-bit words.
__global__ void detect_kernel(const unsigned int* __restrict__ lab32) {
    __shared__ unsigned int s;
    if (threadIdx.x == 0) s = 0u;
    __syncthreads();
    unsigned int w = lab32[threadIdx.x * 2 + 1];
    for (int off = 16; off; off >>= 1)
        w |= __shfl_down_sync(0xffffffffu, w, off);
    if ((threadIdx.x & 31) == 0) atomicOr(&s, w);
    __syncthreads();
    if (threadIdx.x == 0) g_lab64 = (s == 0u) ? 1 : 0;
}

// Fused softmax + binning: 4 pixels per thread via float4 (HW contiguous).
__global__ void __launch_bounds__(256) hist_kernel(const float* __restrict__ x,
                                                   const void* __restrict__ lab) {
    int p4 = blockIdx.x * blockDim.x + threadIdx.x;   // pixel-quad id
    if (p4 >= PIX / 4) return;
    int p  = p4 * 4;
    int b  = p >> 18;            // p / HW
    int hw = p & (HW - 1);
    size_t base = ((size_t)b * CLS) * (size_t)HW + (size_t)hw;

    float4 v[CLS];
    float4 m = make_float4(-1e30f, -1e30f, -1e30f, -1e30f);
#pragma unroll
    for (int c = 0; c < CLS; c++) {
        v[c] = *(const float4*)(x + base + (size_t)c * HW);
        m.x = fmaxf(m.x, v[c].x); m.y = fmaxf(m.y, v[c].y);
        m.z = fmaxf(m.z, v[c].z); m.w = fmaxf(m.w, v[c].w);
    }
    float4 s = make_float4(0.f, 0.f, 0.f, 0.f);
#pragma unroll
    for (int c = 0; c < CLS; c++) {
        v[c].x = __expf(v[c].x - m.x); s.x += v[c].x;
        v[c].y = __expf(v[c].y - m.y); s.y += v[c].y;
        v[c].z = __expf(v[c].z - m.z); s.z += v[c].z;
        v[c].w = __expf(v[c].w - m.w); s.w += v[c].w;
    }
    float4 iz = make_float4(1.f / s.x, 1.f / s.y, 1.f / s.z, 1.f / s.w);

    int l0, l1, l2, l3;
    if (g_lab64) {
        const long long* L = (const long long*)lab;
        l0 = (int)L[p]; l1 = (int)L[p + 1]; l2 = (int)L[p + 2]; l3 = (int)L[p + 3];
    } else {
        int4 L = *(const int4*)((const int*)lab + p);
        l0 = L.x; l1 = L.y; l2 = L.z; l3 = L.w;
    }

#pragma unroll
    for (int c = 0; c < CLS; c++) {
        float pc[4] = { v[c].x * iz.x, v[c].y * iz.y, v[c].z * iz.z, v[c].w * iz.w };
        int   ll[4] = { l0, l1, l2, l3 };
#pragma unroll
        for (int k = 0; k < 4; k++) {
            bool isA = (c == ll[k]);
            float e = isA ? (1.0f - pc[k]) : pc[k];
            e = fminf(fmaxf(e, 0.0f), 1.0f);
            int q = (int)(e * (float)NBINS);
            q = q > (NBINS - 1) ? (NBINS - 1) : q;
            unsigned int* h = isA ? g_cntA : g_cntB;
            atomicAdd(&h[c * NBINS + q], 1u);   // RED.E.ADD.32 (no return)
        }
    }
}

// Per-class descending scan over bins; closed-form Lovasz loss.
//
// Descending-sorted errors with fg flags: an A-element (fg=1) with N B's above
// contributes e/(G+N); a bin's B-elements telescope:
// sum_{j=0}^{nB-1} 1/((GN+j)(GN+j+1)) = nB/(GN*(GN+nB))  [no cancellation].
// Within-bin A/B interleave handled by midpoint correction.
// Per-bin math in fp32 (GN<=2^21 exact); fp64 accumulator only.
__global__ void __launch_bounds__(1024) scan_kernel() {
    const int RPT = NBINS / 1024;   // 8 bins per thread
    int c = blockIdx.x;
    int t = threadIdx.x;
    int base = c * NBINS;
    int r0 = t * RPT;

    __shared__ unsigned int shA[1024];
    __shared__ unsigned int shB[1024];

    unsigned int cA[RPT], cB[RPT];
    unsigned int la = 0, lb = 0;
#pragma unroll
    for (int i = 0; i < RPT; i++) {
        int q = NBINS - 1 - (r0 + i);
        cA[i] = __ldg(&g_cntA[base + q]);
        cB[i] = __ldg(&g_cntB[base + q]);
        la += cA[i]; lb += cB[i];
    }
    shA[t] = la; shB[t] = lb;
    __syncthreads();

    // Inclusive block scan (Hillis-Steele)
    for (int off = 1; off < 1024; off <<= 1) {
        unsigned int va = 0, vb = 0;
        if (t >= off) { va = shA[t - off]; vb = shB[t - off]; }
        __syncthreads();
        shA[t] += va; shB[t] += vb;
        __syncthreads();
    }
    unsigned int totA = shA[1023];
    unsigned int F = shA[t] - la;   // A's strictly above this thread's segment
    unsigned int N = shB[t] - lb;

    const float Gf = (float)totA;
    const float binw = 1.0f / (float)NBINS;
    double loss = 0.0;

#pragma unroll
    for (int i = 0; i < RPT; i++) {
        unsigned int nA = cA[i], nB = cB[i];
        if (nA | nB) {
            int q = NBINS - 1 - (r0 + i);
            float eq  = ((float)q + 0.5f) * binw;       // bin-center error
            float fnA = (float)nA, fnB = (float)nB;
            float GN  = Gf + (float)N;                  // exact (<2^24)
            float term = 0.0f;
            if (nA)
                term += fnA * eq * __fdividef(1.0f, GN + 0.5f * fnB);
            if (nB)
                term += eq * (Gf - (float)F - 0.5f * fnA) * fnB *
                        __fdividef(1.0f, GN * (GN + fnB));
            loss += (double)term;
            F += nA; N += nB;
        }
    }

    // Block-reduce the double accumulator
    for (int off = 16; off; off >>= 1)
        loss += __shfl_down_sync(0xffffffffu, loss, off);
    __shared__ double warpS[32];
    if ((t & 31) == 0) warpS[t >> 5] = loss;
    __syncthreads();
    if (t < 32) {
        double v2 = warpS[t];
        for (int off = 16; off; off >>= 1)
            v2 += __shfl_down_sync(0xffffffffu, v2, off);
        if (t == 0) {
            g_loss[c] = v2;
            g_pres[c] = (totA > 0u) ? 1u : 0u;
        }
    }
}

__global__ void final_kernel(float* out) {
    int t = threadIdx.x;
    double l = 0.0, pcnt = 0.0;
    if (t < CLS && g_pres[t]) { l = g_loss[t]; pcnt = 1.0; }
    for (int off = 16; off; off >>= 1) {
        l    += __shfl_down_sync(0xffffffffu, l, off);
        pcnt += __shfl_down_sync(0xffffffffu, pcnt, off);
    }
    if (t == 0) out[0] = (float)(l / (pcnt > 0.0 ? pcnt : 1.0));
}

extern "C" void kernel_launch(void* const* d_in, const int* in_sizes, int n_in,
                              void* d_out, int out_size) {
    const float* x   = (const float*)d_in[0];
    const void*  lab = d_in[1];
    float*       out = (float*)d_out;

    (void)in_sizes; (void)n_in; (void)out_size;

    zero_kernel<<<(CLS * NBINS + 255) / 256, 256>>>();
    detect_kernel<<<1, 256>>>((const unsigned int*)lab);
    hist_kernel<<<(PIX / 4 + 255) / 256, 256>>>(x, lab);
    scan_kernel<<<CLS, 1024>>>();
    final_kernel<<<1, 32>>>(out);
}